// round 13
// baseline (speedup 1.0000x reference)
#include <cuda_runtime.h>
#include <cuda_bf16.h>
#include <math_constants.h>
#include <cstdint>

// B=512, N=2048, D=128.
// alpha[b,n] = K[b,n] . qtilde[b],  qtilde = Q @ (W1.T@W2) + b1@W2  (b2 cancels in softmax).
// fold_kernel:  Wf = W1.T@W2, c = b1@W2
// qt_kernel:    qtilde = Q @ Wf + c
// attn_main:    flash-style online softmax, SPLIT=2 per batch row, the two halves
//               paired as a 2-CTA cluster. (M,S,acc) exchanged via DSMEM; each CTA
//               writes final normalized weights; rank 0 writes attn_sum. No merge pass.

#define B_ 512
#define N_ 2048
#define D_ 128
#define SPLIT 2
#define CHUNK (N_ / SPLIT)          // 1024
#define UNITS (B_ * SPLIT)          // 1024

__device__ float g_Wf[D_ * D_];
__device__ float g_c[D_];
__device__ float g_qt[B_ * D_];

// ---------------------------------------------------------------------------
__device__ __forceinline__ unsigned int smem_u32(const void* p) {
    return (unsigned int)__cvta_generic_to_shared(p);
}
__device__ __forceinline__ unsigned int mapa_rank(unsigned int local, unsigned int rank) {
    unsigned int r;
    asm("mapa.shared::cluster.u32 %0, %1, %2;" : "=r"(r) : "r"(local), "r"(rank));
    return r;
}
__device__ __forceinline__ float ld_dsmem(unsigned int addr) {
    float v;
    asm volatile("ld.shared::cluster.b32 %0, [%1];" : "=f"(v) : "r"(addr));
    return v;
}

// ---------------------------------------------------------------------------
// Kernel A: Wf[d,t] = sum_e W1[e,d]*W2[e,t] ; block 128 computes c = b1@W2.
// grid = 129, block = 128.
// ---------------------------------------------------------------------------
__global__ void __launch_bounds__(D_) fold_kernel(
    const float* __restrict__ W1, const float* __restrict__ W2,
    const float* __restrict__ b1, float* __restrict__ Wf, float* __restrict__ c)
{
    __shared__ float sv[D_];
    const int d = blockIdx.x;
    const int t = threadIdx.x;
    sv[t] = (d < D_) ? W1[t * D_ + d] : b1[t];
    __syncthreads();
    float acc = 0.f;
#pragma unroll 16
    for (int e = 0; e < D_; e++)
        acc += sv[e] * W2[e * D_ + t];           // coalesced over t
    if (d < D_) Wf[d * D_ + t] = acc;
    else        c[t] = acc;
}

// ---------------------------------------------------------------------------
// Kernel B: qt[b] = Q[b] @ Wf + c.   grid = B, block = 512 (4 threads/output).
// ---------------------------------------------------------------------------
__global__ void __launch_bounds__(512) qt_kernel(
    const float* __restrict__ Q, const float* __restrict__ Wf,
    const float* __restrict__ c, float* __restrict__ qt)
{
    __shared__ float sQ[D_];
    __shared__ float sp[4][D_];
    const int b   = blockIdx.x;
    const int tid = threadIdx.x;
    const int t   = tid & 127;                   // output element
    const int g   = tid >> 7;                    // 0..3, 32-wide d-slice

    if (tid < D_) sQ[tid] = Q[b * D_ + tid];
    __syncthreads();

    float acc = 0.f;
#pragma unroll 8
    for (int i = 0; i < 32; i++) {
        const int d = g * 32 + i;
        acc += sQ[d] * Wf[d * D_ + t];           // coalesced over t
    }
    sp[g][t] = acc;
    __syncthreads();

    if (tid < D_)
        qt[b * D_ + tid] = sp[0][tid] + sp[1][tid] + sp[2][tid] + sp[3][tid] + c[tid];
}

// ---------------------------------------------------------------------------
// Kernel C: per-(b,part) single-pass online softmax over CHUNK rows.
// grid = UNITS (1024), block = 1024 (32 warps), cluster = 2 (the two halves of b).
// ---------------------------------------------------------------------------
__global__ void __launch_bounds__(1024, 1) __cluster_dims__(2, 1, 1)
attn_main(
    const float* __restrict__ K, const float* __restrict__ V,
    const float* __restrict__ adj, const float* __restrict__ qt,
    float* __restrict__ attn_w, float* __restrict__ attn_sum)
{
    __shared__ float s_alpha[CHUNK];       // 4 KB
    __shared__ float s_acc[32][D_];        // 16 KB
    __shared__ float s_m[32], s_s[32];
    __shared__ float s_MS[2];
    __shared__ float s_final[D_ + 2];      // acc total + {M, S}  (DSMEM-exported)
    __shared__ float s_peerMS[2];

    const int u    = blockIdx.x;
    const int b    = u >> 1;
    const int rank = u & 1;                // == cluster_ctarank
    const int tid  = threadIdx.x;
    const int lane = tid & 31;
    const int warp = tid >> 5;             // 0..31
    const int base = rank * CHUNK;

    const float4* __restrict__ K4   = (const float4*)(K + (size_t)b * N_ * D_);
    const float4* __restrict__ V4   = (const float4*)(V + (size_t)b * N_ * D_);
    const float*  __restrict__ adjb = adj + (size_t)b * N_;

    const float4 q = *((const float4*)(qt + b * D_) + lane);

    float  m = -CUDART_INF_F;
    float  s = 0.f;
    float4 acc = make_float4(0.f, 0.f, 0.f, 0.f);

    // warp handles rows n = base + warp + 32*j; 2 rows per iteration.
#pragma unroll 4
    for (int jj = 0; jj < 16; jj++) {
        const int    n0 = base + 64 * jj + warp;          // second row: n0+32
        const size_t o0 = (size_t)n0 * 32 + lane;         // float4 offset
        float4 k0 = __ldcs(&K4[o0]);
        float4 k1 = __ldcs(&K4[o0 + 1024]);               // +32 rows
        float4 v0 = __ldcs(&V4[o0]);
        float4 v1 = __ldcs(&V4[o0 + 1024]);
        float adj0 = __ldcs(&adjb[n0]);
        float adj1 = __ldcs(&adjb[n0 + 32]);

        float p0 = k0.x*q.x + k0.y*q.y + k0.z*q.z + k0.w*q.w;
        float p1 = k1.x*q.x + k1.y*q.y + k1.z*q.z + k1.w*q.w;
#pragma unroll
        for (int o = 16; o; o >>= 1) {
            p0 += __shfl_xor_sync(0xffffffffu, p0, o);
            p1 += __shfl_xor_sync(0xffffffffu, p1, o);
        }
        float a0 = p0 - (1.f - adj0) * 1e30f;
        float a1 = p1 - (1.f - adj1) * 1e30f;
        if (lane == 0) {
            s_alpha[64 * jj + warp]      = a0;
            s_alpha[64 * jj + warp + 32] = a1;
        }

        float nm = fmaxf(m, fmaxf(a0, a1));
        float f  = __expf(m - nm);
        float e0 = __expf(a0 - nm);
        float e1 = __expf(a1 - nm);
        s = s * f + e0 + e1;
        acc.x = acc.x * f + e0 * v0.x + e1 * v1.x;
        acc.y = acc.y * f + e0 * v0.y + e1 * v1.y;
        acc.z = acc.z * f + e0 * v0.z + e1 * v1.z;
        acc.w = acc.w * f + e0 * v0.w + e1 * v1.w;
        m = nm;
    }

    // ---- CTA merge of 32 warp partials ----
    if (lane == 0) { s_m[warp] = m; s_s[warp] = s; }
    *(float4*)&s_acc[warp][lane * 4] = acc;
    __syncthreads();

    if (warp == 0) {
        float mw = s_m[lane];
        float M  = mw;
#pragma unroll
        for (int o = 16; o; o >>= 1) M = fmaxf(M, __shfl_xor_sync(0xffffffffu, M, o));
        float sw = s_s[lane] * __expf(mw - M);
#pragma unroll
        for (int o = 16; o; o >>= 1) sw += __shfl_xor_sync(0xffffffffu, sw, o);
        if (lane == 0) { s_MS[0] = M; s_MS[1] = sw; }
    }
    __syncthreads();
    const float M = s_MS[0];

    // stage 2: 8 groups of 128 threads each fold 4 scaled warp partials
    const int g = tid >> 7;
    const int d = tid & 127;
    float p4 = 0.f;
#pragma unroll
    for (int w = 0; w < 4; w++) {
        const int wi = g * 4 + w;
        p4 += s_acc[wi][d] * __expf(s_m[wi] - M);
    }
    __syncthreads();                       // all reads of s_acc done
    s_acc[g][d] = p4;
    __syncthreads();

    if (tid < D_) {
        float tot = 0.f;
#pragma unroll
        for (int gg = 0; gg < 8; gg++) tot += s_acc[gg][tid];
        s_final[tid] = tot;
    }
    if (tid == 0) { s_final[D_] = M; s_final[D_ + 1] = s_MS[1]; }
    __syncthreads();   // s_final complete before cluster barrier

    // ---- cluster exchange of (M, S, acc) ----
    asm volatile("barrier.cluster.arrive.aligned;" ::: "memory");
    asm volatile("barrier.cluster.wait.aligned;"   ::: "memory");

    const unsigned int peer = (unsigned int)(rank ^ 1);
    if (tid < 2) {
        const unsigned int a = mapa_rank(smem_u32(&s_final[D_ + tid]), peer);
        s_peerMS[tid] = ld_dsmem(a);
    }
    __syncthreads();

    const float Mp = s_peerMS[0];
    const float Sp = s_peerMS[1];
    const float Mg = fmaxf(M, Mp);
    const float es = __expf(M  - Mg);
    const float ep = __expf(Mp - Mg);
    const float inv = 1.f / (s_MS[1] * es + Sp * ep);

    // final normalized weight writeout (CHUNK == blockDim)
    attn_w[(size_t)b * N_ + base + tid] = __expf(s_alpha[tid] - Mg) * inv;

    if (rank == 0 && tid < D_) {
        const float pacc = ld_dsmem(mapa_rank(smem_u32(&s_final[tid]), peer));
        attn_sum[(size_t)b * D_ + tid] = (s_final[tid] * es + pacc * ep) * inv;
    }

    // keep peer smem alive until all DSMEM reads are done
    asm volatile("barrier.cluster.arrive.aligned;" ::: "memory");
    asm volatile("barrier.cluster.wait.aligned;"   ::: "memory");
}

// ---------------------------------------------------------------------------
extern "C" void kernel_launch(void* const* d_in, const int* in_sizes, int n_in,
                              void* d_out, int out_size)
{
    const float* Q   = (const float*)d_in[0];   // (B,D)
    const float* K   = (const float*)d_in[1];   // (B,N,D)
    const float* V   = (const float*)d_in[2];   // (B,N,D)
    const float* adj = (const float*)d_in[3];   // (B,N)
    // d_in[4] = s_mask (unused)
    const float* W1  = (const float*)d_in[5];   // (D,D)
    const float* b1  = (const float*)d_in[6];   // (D,)
    const float* W2  = (const float*)d_in[7];   // (D,D)
    // d_in[8] = b2 (cancels in softmax)

    float* out_w   = (float*)d_out;                      // (B,1,N)
    float* out_sum = (float*)d_out + (size_t)B_ * N_;    // (B,D)

    float *Wf, *cv, *qt;
    cudaGetSymbolAddress((void**)&Wf, g_Wf);
    cudaGetSymbolAddress((void**)&cv, g_c);
    cudaGetSymbolAddress((void**)&qt, g_qt);

    fold_kernel<<<D_ + 1, D_>>>(W1, W2, b1, Wf, cv);
    qt_kernel<<<B_, 512>>>(Q, Wf, cv, qt);
    attn_main<<<UNITS, 1024>>>(K, V, adj, qt, out_w, out_sum);
}

// round 14
// speedup vs baseline: 1.0927x; 1.0927x over previous
#include <cuda_runtime.h>
#include <cuda_bf16.h>
#include <math_constants.h>
#include <cstdint>

// B=512, N=2048, D=128.
// alpha[b,n] = K[b,n] . qtilde[b],  qtilde = Q @ (W1.T@W2) + b1@W2  (b2 cancels in softmax).
// fold_kernel:  Wf = W1.T@W2, c = b1@W2        (k-split x4)
// qt_kernel:    qtilde = Q @ Wf + c            (k-split x4)
// attn_main:    flash-style online softmax streaming K & V together, SPLIT=2,
//               epilogue writes exp(alpha - M_cta) (unnormalized)
// merge_kernel: per-b exp-free rescale of both halves + attn_sum combine (ILP 2).

#define B_ 512
#define N_ 2048
#define D_ 128
#define SPLIT 2
#define CHUNK (N_ / SPLIT)          // 1024
#define UNITS (B_ * SPLIT)          // 1024

__device__ float g_Wf[D_ * D_];
__device__ float g_c[D_];
__device__ float g_qt[B_ * D_];
__device__ float g_pm[UNITS];
__device__ float g_ps[UNITS];
__device__ float g_pacc[UNITS * D_];

// ---------------------------------------------------------------------------
// Kernel A: Wf[d,t] = sum_e W1[e,d]*W2[e,t] ; block 128 computes c = b1@W2.
// grid = 129, block = 512 (4-way k-split per output).
// ---------------------------------------------------------------------------
__global__ void __launch_bounds__(512) fold_kernel(
    const float* __restrict__ W1, const float* __restrict__ W2,
    const float* __restrict__ b1, float* __restrict__ Wf, float* __restrict__ c)
{
    __shared__ float sv[D_];
    __shared__ float sp[4][D_];
    const int d   = blockIdx.x;
    const int tid = threadIdx.x;
    const int t   = tid & 127;
    const int g   = tid >> 7;                    // 0..3

    if (tid < D_) sv[tid] = (d < D_) ? W1[tid * D_ + d] : b1[tid];
    __syncthreads();

    float acc = 0.f;
#pragma unroll 8
    for (int i = 0; i < 32; i++) {
        const int e = g * 32 + i;
        acc += sv[e] * W2[e * D_ + t];           // coalesced over t
    }
    sp[g][t] = acc;
    __syncthreads();

    if (tid < D_) {
        const float r = sp[0][tid] + sp[1][tid] + sp[2][tid] + sp[3][tid];
        if (d < D_) Wf[d * D_ + tid] = r;
        else        c[tid] = r;
    }
}

// ---------------------------------------------------------------------------
// Kernel B: qt[b] = Q[b] @ Wf + c.   grid = B, block = 512 (4 threads/output).
// ---------------------------------------------------------------------------
__global__ void __launch_bounds__(512) qt_kernel(
    const float* __restrict__ Q, const float* __restrict__ Wf,
    const float* __restrict__ c, float* __restrict__ qt)
{
    __shared__ float sQ[D_];
    __shared__ float sp[4][D_];
    const int b   = blockIdx.x;
    const int tid = threadIdx.x;
    const int t   = tid & 127;                   // output element
    const int g   = tid >> 7;                    // 0..3, 32-wide d-slice

    if (tid < D_) sQ[tid] = Q[b * D_ + tid];
    __syncthreads();

    float acc = 0.f;
#pragma unroll 8
    for (int i = 0; i < 32; i++) {
        const int d = g * 32 + i;
        acc += sQ[d] * Wf[d * D_ + t];           // coalesced over t
    }
    sp[g][t] = acc;
    __syncthreads();

    if (tid < D_)
        qt[b * D_ + tid] = sp[0][tid] + sp[1][tid] + sp[2][tid] + sp[3][tid] + c[tid];
}

// ---------------------------------------------------------------------------
// Kernel C: per-(b,part) single-pass online softmax over CHUNK rows.
// grid = UNITS (1024), block = 1024 (32 warps).
// Writes exp(alpha - M_cta) into attn_w and (m,s,acc[128]) partials.
// ---------------------------------------------------------------------------
__global__ void __launch_bounds__(1024, 1) attn_main(
    const float* __restrict__ K, const float* __restrict__ V,
    const float* __restrict__ adj, const float* __restrict__ qt,
    float* __restrict__ attn_w)
{
    __shared__ float s_alpha[CHUNK];       // 4 KB
    __shared__ float s_acc[32][D_];        // 16 KB
    __shared__ float s_m[32], s_s[32];
    __shared__ float s_MS[2];

    const int u    = blockIdx.x;
    const int b    = u >> 1;
    const int part = u & 1;
    const int tid  = threadIdx.x;
    const int lane = tid & 31;
    const int warp = tid >> 5;             // 0..31
    const int base = part * CHUNK;

    const float4* __restrict__ K4   = (const float4*)(K + (size_t)b * N_ * D_);
    const float4* __restrict__ V4   = (const float4*)(V + (size_t)b * N_ * D_);
    const float*  __restrict__ adjb = adj + (size_t)b * N_;

    const float4 q = *((const float4*)(qt + b * D_) + lane);

    float  m = -CUDART_INF_F;
    float  s = 0.f;
    float4 acc = make_float4(0.f, 0.f, 0.f, 0.f);

    // warp handles rows n = base + warp + 32*j; 2 rows per iteration.
#pragma unroll 4
    for (int jj = 0; jj < 16; jj++) {
        const int    n0 = base + 64 * jj + warp;          // second row: n0+32
        const size_t o0 = (size_t)n0 * 32 + lane;         // float4 offset
        float4 k0 = __ldcs(&K4[o0]);
        float4 k1 = __ldcs(&K4[o0 + 1024]);               // +32 rows
        float4 v0 = __ldcs(&V4[o0]);
        float4 v1 = __ldcs(&V4[o0 + 1024]);
        float adj0 = __ldcs(&adjb[n0]);
        float adj1 = __ldcs(&adjb[n0 + 32]);

        float p0 = k0.x*q.x + k0.y*q.y + k0.z*q.z + k0.w*q.w;
        float p1 = k1.x*q.x + k1.y*q.y + k1.z*q.z + k1.w*q.w;
#pragma unroll
        for (int o = 16; o; o >>= 1) {
            p0 += __shfl_xor_sync(0xffffffffu, p0, o);
            p1 += __shfl_xor_sync(0xffffffffu, p1, o);
        }
        float a0 = p0 - (1.f - adj0) * 1e30f;
        float a1 = p1 - (1.f - adj1) * 1e30f;
        if (lane == 0) {
            s_alpha[64 * jj + warp]      = a0;
            s_alpha[64 * jj + warp + 32] = a1;
        }

        // a0/a1/m are warp-uniform: the rescale branch is divergence-free and
        // usually not taken (running max rarely updates).
        const float nm = fmaxf(m, fmaxf(a0, a1));
        if (nm > m) {
            const float f = __expf(m - nm);   // m=-inf first time -> f=0
            s *= f;
            acc.x *= f; acc.y *= f; acc.z *= f; acc.w *= f;
            m = nm;
        }
        const float e0 = __expf(a0 - m);
        const float e1 = __expf(a1 - m);
        s += e0 + e1;
        acc.x += e0 * v0.x + e1 * v1.x;
        acc.y += e0 * v0.y + e1 * v1.y;
        acc.z += e0 * v0.z + e1 * v1.z;
        acc.w += e0 * v0.w + e1 * v1.w;
    }

    // ---- CTA merge of 32 warp partials ----
    if (lane == 0) { s_m[warp] = m; s_s[warp] = s; }
    *(float4*)&s_acc[warp][lane * 4] = acc;
    __syncthreads();

    if (warp == 0) {
        float mw = s_m[lane];
        float M  = mw;
#pragma unroll
        for (int o = 16; o; o >>= 1) M = fmaxf(M, __shfl_xor_sync(0xffffffffu, M, o));
        float sw = s_s[lane] * __expf(mw - M);
#pragma unroll
        for (int o = 16; o; o >>= 1) sw += __shfl_xor_sync(0xffffffffu, sw, o);
        if (lane == 0) { s_MS[0] = M; s_MS[1] = sw; }
    }
    __syncthreads();
    const float M = s_MS[0];

    // stage 2: 8 groups of 128 threads each fold 4 scaled warp partials
    const int g = tid >> 7;
    const int d = tid & 127;
    float p4 = 0.f;
#pragma unroll
    for (int w = 0; w < 4; w++) {
        const int wi = g * 4 + w;
        p4 += s_acc[wi][d] * __expf(s_m[wi] - M);
    }
    __syncthreads();                       // all reads of s_acc done
    s_acc[g][d] = p4;

    // writeout: exp(alpha - M_cta), unnormalized (CHUNK == blockDim)
    attn_w[(size_t)u * CHUNK + tid] = __expf(s_alpha[tid] - M);
    __syncthreads();

    if (tid < D_) {
        float tot = 0.f;
#pragma unroll
        for (int gg = 0; gg < 8; gg++) tot += s_acc[gg][tid];
        g_pacc[(size_t)u * D_ + tid] = tot;
        if (tid == 0) { g_pm[u] = M; g_ps[u] = s_MS[1]; }
    }
}

// ---------------------------------------------------------------------------
// Kernel D: exp-free merge, one CTA per b. block = 256; each thread rescales
// one float4 from EACH half (ILP 2) and tid<128 writes attn_sum.
// ---------------------------------------------------------------------------
__global__ void __launch_bounds__(256) merge_kernel(
    float* __restrict__ attn_w, float* __restrict__ attn_sum)
{
    const int b   = blockIdx.x;
    const int tid = threadIdx.x;
    const int u0  = b * 2, u1 = u0 + 1;

    const float m0 = g_pm[u0], m1 = g_pm[u1];
    const float M  = fmaxf(m0, m1);
    const float e0 = __expf(m0 - M);
    const float e1 = __expf(m1 - M);
    const float inv = 1.f / (g_ps[u0] * e0 + g_ps[u1] * e1);
    const float sc0 = e0 * inv;
    const float sc1 = e1 * inv;

    float4* wp = (float4*)(attn_w + (size_t)b * N_);   // 512 float4s total
    float4 v0 = wp[tid];                               // half 0: [0,256)
    float4 v1 = wp[tid + 256];                         // half 1: [256,512)
    v0.x *= sc0; v0.y *= sc0; v0.z *= sc0; v0.w *= sc0;
    v1.x *= sc1; v1.y *= sc1; v1.z *= sc1; v1.w *= sc1;
    wp[tid]       = v0;
    wp[tid + 256] = v1;

    if (tid < D_)
        attn_sum[(size_t)b * D_ + tid] =
            g_pacc[(size_t)u0 * D_ + tid] * sc0 + g_pacc[(size_t)u1 * D_ + tid] * sc1;
}

// ---------------------------------------------------------------------------
extern "C" void kernel_launch(void* const* d_in, const int* in_sizes, int n_in,
                              void* d_out, int out_size)
{
    const float* Q   = (const float*)d_in[0];   // (B,D)
    const float* K   = (const float*)d_in[1];   // (B,N,D)
    const float* V   = (const float*)d_in[2];   // (B,N,D)
    const float* adj = (const float*)d_in[3];   // (B,N)
    // d_in[4] = s_mask (unused)
    const float* W1  = (const float*)d_in[5];   // (D,D)
    const float* b1  = (const float*)d_in[6];   // (D,)
    const float* W2  = (const float*)d_in[7];   // (D,D)
    // d_in[8] = b2 (cancels in softmax)

    float* out_w   = (float*)d_out;                      // (B,1,N)
    float* out_sum = (float*)d_out + (size_t)B_ * N_;    // (B,D)

    float *Wf, *cv, *qt;
    cudaGetSymbolAddress((void**)&Wf, g_Wf);
    cudaGetSymbolAddress((void**)&cv, g_c);
    cudaGetSymbolAddress((void**)&qt, g_qt);

    fold_kernel<<<D_ + 1, 512>>>(W1, W2, b1, Wf, cv);
    qt_kernel<<<B_, 512>>>(Q, Wf, cv, qt);
    attn_main<<<UNITS, 1024>>>(K, V, adj, qt, out_w);
    merge_kernel<<<B_, 256>>>(out_w, out_sum);
}